// round 1
// baseline (speedup 1.0000x reference)
#include <cuda_runtime.h>
#include <math.h>

// Problem constants
#define BGR   128          // graphs
#define N0    1024         // nodes per graph (layer 1)
#define NTOT  131072       // B*N0
#define ETOT  2097152      // B*N0*16 edges
#define DD    64
#define K1    820
#define K2    656
#define K3    525

#define NEG_INF __int_as_float(0xff800000)

// ---------------- scratch (device globals; no allocation allowed) ----------
__device__ float g_x[NTOT * DD];      // current node features (layer input)
__device__ float g_y[NTOT * DD];      // sage output
__device__ float g_msg[NTOT * DD];
__device__ float g_aggr[NTOT * DD];
__device__ float g_score[NTOT];
__device__ int   g_selold[NTOT];
__device__ float g_selscale[NTOT];
__device__ int   g_inv[NTOT];
__device__ int   g_esrc[2][ETOT];
__device__ int   g_edst[2][ETOT];
__device__ unsigned char g_emask[2][ETOT];
__device__ float g_h[BGR * 2 * DD];   // readout accumulator [B,128]

// ---------------- kernels --------------------------------------------------

__global__ void k_embed(const int* __restrict__ x_ids,
                        const float* __restrict__ emb) {
    int i = blockIdx.x * blockDim.x + threadIdx.x;
    if (i < NTOT * DD)
        g_x[i] = emb[x_ids[i >> 6] * DD + (i & 63)];
}

__global__ void k_zero_h() {
    int i = blockIdx.x * blockDim.x + threadIdx.x;
    if (i < BGR * 2 * DD) g_h[i] = 0.f;
}

// msg = relu(x @ W^T + b); also aggr = msg (self-loop init for max-aggr)
__global__ void k_gemm64(const float* __restrict__ W,
                         const float* __restrict__ bias, int n) {
    __shared__ float Wt[64][64];   // Wt[i][o] = W[o*64+i]
    for (int t = threadIdx.x; t < 64 * 64; t += blockDim.x) {
        int o = t >> 6, i = t & 63;
        Wt[i][o] = W[t];
    }
    __syncthreads();
    int row = blockIdx.x * blockDim.x + threadIdx.x;
    if (row >= n) return;
    const float* xr = g_x + (size_t)row * DD;
    float acc[64];
#pragma unroll
    for (int o = 0; o < 64; o++) acc[o] = bias[o];
#pragma unroll 8
    for (int i = 0; i < 64; i++) {
        float xv = xr[i];
#pragma unroll
        for (int o = 0; o < 64; o++) acc[o] = fmaf(xv, Wt[i][o], acc[o]);
    }
    float* m = g_msg  + (size_t)row * DD;
    float* a = g_aggr + (size_t)row * DD;
#pragma unroll
    for (int o = 0; o < 64; o++) {
        float v = acc[o] > 0.f ? acc[o] : 0.f;
        m[o] = v; a[o] = v;
    }
}

// segment max over edges: aggr[dst] = max(aggr[dst], msg[src])
// values >= 0 so int atomicMax on float bits is order-preserving.
__global__ void k_scatter(const int* __restrict__ src_ext,
                          const int* __restrict__ dst_ext,
                          const unsigned char* __restrict__ mask_ext,
                          int bank) {
    int idx = blockIdx.x * blockDim.x + threadIdx.x;
    int e = idx >> 4, c = idx & 15;
    if (e >= ETOT) return;
    const int* src = (bank < 0) ? src_ext : g_esrc[bank];
    const int* dst = (bank < 0) ? dst_ext : g_edst[bank];
    if (bank >= 0) { if (!g_emask[bank][e]) return; }
    else if (mask_ext) { if (!mask_ext[e]) return; }
    int s = src[e], d = dst[e];
    float4 v = ((const float4*)g_msg)[(size_t)s * 16 + c];
    int* a = ((int*)g_aggr) + (size_t)d * DD + c * 4;
    atomicMax(a + 0, __float_as_int(v.x));
    atomicMax(a + 1, __float_as_int(v.y));
    atomicMax(a + 2, __float_as_int(v.z));
    atomicMax(a + 3, __float_as_int(v.w));
}

// y = relu( [aggr | x] @ U^T )   U: [64,128] row-major
__global__ void k_gemmcat(const float* __restrict__ U, int n) {
    __shared__ float Ut[128][64];  // Ut[i][o] = U[o*128+i]
    for (int t = threadIdx.x; t < 128 * 64; t += blockDim.x) {
        int o = t >> 7, i = t & 127;
        Ut[i][o] = U[t];
    }
    __syncthreads();
    int row = blockIdx.x * blockDim.x + threadIdx.x;
    if (row >= n) return;
    const float* ar = g_aggr + (size_t)row * DD;
    const float* xr = g_x   + (size_t)row * DD;
    float acc[64];
#pragma unroll
    for (int o = 0; o < 64; o++) acc[o] = 0.f;
#pragma unroll 4
    for (int i = 0; i < 64; i++) {
        float av = ar[i];
#pragma unroll
        for (int o = 0; o < 64; o++) acc[o] = fmaf(av, Ut[i][o], acc[o]);
    }
#pragma unroll 4
    for (int i = 0; i < 64; i++) {
        float xv = xr[i];
#pragma unroll
        for (int o = 0; o < 64; o++) acc[o] = fmaf(xv, Ut[64 + i][o], acc[o]);
    }
    float* yr = g_y + (size_t)row * DD;
#pragma unroll
    for (int o = 0; o < 64; o++) yr[o] = acc[o] > 0.f ? acc[o] : 0.f;
}

// score = (y . p) / ||p||
__global__ void k_score(const float* __restrict__ p, int n) {
    __shared__ float ps[64];
    __shared__ float pinv;
    if (threadIdx.x < 64) ps[threadIdx.x] = p[threadIdx.x];
    __syncthreads();
    if (threadIdx.x == 0) {
        float s = 0.f;
        for (int i = 0; i < 64; i++) s += ps[i] * ps[i];
        pinv = 1.0f / sqrtf(s);
    }
    __syncthreads();
    int row = blockIdx.x * blockDim.x + threadIdx.x;
    if (row >= n) return;
    const float* yr = g_y + (size_t)row * DD;
    float s = 0.f;
#pragma unroll
    for (int i = 0; i < 64; i++) s += yr[i] * ps[i];
    g_score[row] = s * pinv;
}

// per-graph exact top-k via bitonic sort of 1024 (score, idx) pairs
__global__ void k_topk(int n_per, int k) {
    __shared__ float sc[1024];
    __shared__ int   si[1024];
    int b = blockIdx.x;
    int t = threadIdx.x;
    if (t < n_per) g_inv[b * n_per + t] = -1;
    sc[t] = (t < n_per) ? g_score[b * n_per + t] : NEG_INF;
    si[t] = t;
    __syncthreads();
    for (int ksz = 2; ksz <= 1024; ksz <<= 1) {
        for (int j = ksz >> 1; j > 0; j >>= 1) {
            int l = t ^ j;
            if (l > t) {
                bool dirDesc = ((t & ksz) == 0);
                float a = sc[t], c = sc[l];
                int ia = si[t], ic = si[l];
                bool aFirst = (a > c) || (a == c && ia < ic);
                if (aFirst != dirDesc) {
                    sc[t] = c; sc[l] = a;
                    si[t] = ic; si[l] = ia;
                }
            }
            __syncthreads();
        }
    }
    if (t < k) {
        int old = b * n_per + si[t];
        int nw  = b * k + t;
        g_selold[nw]   = old;
        g_selscale[nw] = tanhf(sc[t]);
        g_inv[old]     = nw;
    }
}

// x_new[j] = y[sel[j]] * scale[j]
__global__ void k_gather(int nk) {
    int idx = blockIdx.x * blockDim.x + threadIdx.x;
    if (idx >= nk * DD) return;
    int j = idx >> 6, d = idx & 63;
    g_x[idx] = g_y[(size_t)g_selold[j] * DD + d] * g_selscale[j];
}

__global__ void k_remap(const int* __restrict__ src_ext,
                        const int* __restrict__ dst_ext,
                        const unsigned char* __restrict__ mask_ext,
                        int in_bank, int out_bank) {
    int e = blockIdx.x * blockDim.x + threadIdx.x;
    if (e >= ETOT) return;
    const int* src = (in_bank < 0) ? src_ext : g_esrc[in_bank];
    const int* dst = (in_bank < 0) ? dst_ext : g_edst[in_bank];
    bool m;
    if (in_bank >= 0) m = g_emask[in_bank][e] != 0;
    else              m = mask_ext ? (mask_ext[e] != 0) : true;
    int ns = 0, nd = 0; bool nm = false;
    if (m) {
        ns = g_inv[src[e]];
        nd = g_inv[dst[e]];
        nm = (ns >= 0) && (nd >= 0);
    }
    g_esrc[out_bank][e]  = nm ? ns : 0;
    g_edst[out_bank][e]  = nm ? nd : 0;
    g_emask[out_bank][e] = nm ? 1 : 0;
}

// h[b] += [ max_j x , mean_j x ]
__global__ void k_readout(int k) {
    int b = blockIdx.x;
    int d = threadIdx.x;  // 64 threads
    float mx = NEG_INF, sm = 0.f;
    const float* base = g_x + (size_t)b * k * DD + d;
    for (int j = 0; j < k; j++) {
        float v = base[(size_t)j * DD];
        mx = fmaxf(mx, v);
        sm += v;
    }
    g_h[b * 128 + d]      += mx;
    g_h[b * 128 + 64 + d] += sm / (float)k;
}

__global__ void k_mlp(const float* __restrict__ l1W, const float* __restrict__ l1b,
                      const float* __restrict__ l2W, const float* __restrict__ l2b,
                      const float* __restrict__ l3W, const float* __restrict__ l3b,
                      float* __restrict__ out) {
    int b = blockIdx.x;
    int o = threadIdx.x;  // 64
    __shared__ float h[128], s1[64], s2[64];
    h[o]      = g_h[b * 128 + o];
    h[o + 64] = g_h[b * 128 + 64 + o];
    __syncthreads();
    float a = l1b[o];
#pragma unroll 8
    for (int i = 0; i < 128; i++) a = fmaf(h[i], l1W[o * 128 + i], a);
    s1[o] = fmaxf(a, 0.f);
    __syncthreads();
    a = l2b[o];
#pragma unroll 8
    for (int i = 0; i < 64; i++) a = fmaf(s1[i], l2W[o * 64 + i], a);
    s2[o] = fmaxf(a, 0.f);
    __syncthreads();
    a = l3b[o];
#pragma unroll 8
    for (int i = 0; i < 64; i++) a = fmaf(s2[i], l3W[o * 64 + i], a);
    out[b * 64 + o] = 1.f / (1.f + expf(-a));
}

__global__ void k_batch(float* __restrict__ out, int out_size) {
    int i = blockIdx.x * blockDim.x + threadIdx.x;
    if (i >= BGR * K3) return;
    int pos = 8192 + i;
    if (pos < out_size) out[pos] = (float)(i / K3);
}

// ---------------- host orchestration ---------------------------------------

static void run_layer(int n, int n_per, int k,
                      const float* W, const float* b, const float* U, const float* p,
                      const int* src_ext, const int* dst_ext,
                      const unsigned char* mask_ext,
                      int in_bank, int out_bank, bool do_remap) {
    int gb = (n + 127) / 128;
    k_gemm64<<<gb, 128>>>(W, b, n);
    int sb = (ETOT * 16 + 255) / 256;
    k_scatter<<<sb, 256>>>(src_ext, dst_ext, mask_ext, in_bank);
    k_gemmcat<<<gb, 128>>>(U, n);
    k_score<<<(n + 255) / 256, 256>>>(p, n);
    k_topk<<<BGR, 1024>>>(n_per, k);
    int nk = BGR * k;
    k_gather<<<(nk * DD + 255) / 256, 256>>>(nk);
    if (do_remap)
        k_remap<<<(ETOT + 255) / 256, 256>>>(src_ext, dst_ext, mask_ext,
                                             in_bank, out_bank);
    k_readout<<<BGR, 64>>>(k);
}

extern "C" void kernel_launch(void* const* d_in, const int* in_sizes, int n_in,
                              void* d_out, int out_size) {
    const int*   x_ids = (const int*)d_in[0];
    const int*   eidx  = (const int*)d_in[1];   // [2, E]
    const float* emb   = (const float*)d_in[2];
    const float* W1 = (const float*)d_in[3];
    const float* b1 = (const float*)d_in[4];
    const float* U1 = (const float*)d_in[5];
    const float* p1 = (const float*)d_in[6];
    const float* W2 = (const float*)d_in[7];
    const float* b2 = (const float*)d_in[8];
    const float* U2 = (const float*)d_in[9];
    const float* p2 = (const float*)d_in[10];
    const float* W3 = (const float*)d_in[11];
    const float* b3 = (const float*)d_in[12];
    const float* U3 = (const float*)d_in[13];
    const float* p3 = (const float*)d_in[14];
    const float* l1W = (const float*)d_in[15];
    const float* l1b = (const float*)d_in[16];
    const float* l2W = (const float*)d_in[17];
    const float* l2b = (const float*)d_in[18];
    const float* l3W = (const float*)d_in[19];
    const float* l3b = (const float*)d_in[20];
    float* out = (float*)d_out;

    k_embed<<<(NTOT * DD + 255) / 256, 256>>>(x_ids, emb);
    k_zero_h<<<(BGR * 2 * DD + 255) / 256, 256>>>();

    // layer 1: n = 131072, edges from input, write bank 0
    run_layer(NTOT, N0, K1, W1, b1, U1, p1,
              eidx, eidx + ETOT, nullptr, -1, 0, true);
    // layer 2: n = B*K1, edges bank0 -> bank1
    run_layer(BGR * K1, K1, K2, W2, b2, U2, p2,
              nullptr, nullptr, nullptr, 0, 1, true);
    // layer 3: n = B*K2, edges bank1, no remap needed after
    run_layer(BGR * K2, K2, K3, W3, b3, U3, p3,
              nullptr, nullptr, nullptr, 1, 0, false);

    k_mlp<<<BGR, 64>>>(l1W, l1b, l2W, l2b, l3W, l3b, out);
    k_batch<<<(BGR * K3 + 255) / 256, 256>>>(out, out_size);
}

// round 2
// speedup vs baseline: 1.5579x; 1.5579x over previous
#include <cuda_runtime.h>
#include <math.h>

// Problem constants
#define BGR   128          // graphs
#define N0    1024         // nodes per graph (layer 1)
#define NTOT  131072       // B*N0
#define ETOT  2097152      // B*N0*16 edges
#define EPG   16384        // edges per graph
#define DD    64
#define K1    820
#define K2    656
#define K3    525

#define NEG_INF __int_as_float(0xff800000)

// ---------------- scratch (device globals; no allocation allowed) ----------
__device__ float g_x[NTOT * DD];      // current node features (layer input)
__device__ float g_y[NTOT * DD];      // sage output
__device__ float g_msg[NTOT * DD];
__device__ float g_aggr[NTOT * DD];
__device__ float g_score[NTOT];
__device__ int   g_selold[NTOT];
__device__ float g_selscale[NTOT];
__device__ int   g_inv[NTOT];
__device__ int   g_esrc[2][ETOT];
__device__ int   g_edst[2][ETOT];
__device__ unsigned char g_emask[2][ETOT];
__device__ float g_h[BGR * 2 * DD];   // readout accumulator [B,128]
// CSR scratch
__device__ int   g_deg[NTOT];
__device__ int   g_headp[NTOT];
__device__ int   g_cur[NTOT];
__device__ int   g_csr[ETOT];

// ---------------- kernels --------------------------------------------------

__global__ void k_embed(const int* __restrict__ x_ids,
                        const float* __restrict__ emb) {
    int i = blockIdx.x * blockDim.x + threadIdx.x;
    if (i < NTOT * DD)
        g_x[i] = emb[x_ids[i >> 6] * DD + (i & 63)];
}

__global__ void k_zero_h() {
    int i = blockIdx.x * blockDim.x + threadIdx.x;
    if (i < BGR * 2 * DD) g_h[i] = 0.f;
}

__global__ void k_zero_deg(int n) {
    int i = blockIdx.x * blockDim.x + threadIdx.x;
    if (i < n) g_deg[i] = 0;
}

// msg = relu(x @ W^T + b)
__global__ void k_gemm64(const float* __restrict__ W,
                         const float* __restrict__ bias, int n) {
    __shared__ float Wt[64][64];   // Wt[i][o] = W[o*64+i]
    for (int t = threadIdx.x; t < 64 * 64; t += blockDim.x) {
        int o = t >> 6, i = t & 63;
        Wt[i][o] = W[t];
    }
    __syncthreads();
    int row = blockIdx.x * blockDim.x + threadIdx.x;
    if (row >= n) return;
    const float* xr = g_x + (size_t)row * DD;
    float acc[64];
#pragma unroll
    for (int o = 0; o < 64; o++) acc[o] = bias[o];
#pragma unroll 8
    for (int i = 0; i < 64; i++) {
        float xv = xr[i];
#pragma unroll
        for (int o = 0; o < 64; o++) acc[o] = fmaf(xv, Wt[i][o], acc[o]);
    }
    float* m = g_msg + (size_t)row * DD;
#pragma unroll
    for (int o = 0; o < 64; o++) m[o] = acc[o] > 0.f ? acc[o] : 0.f;
}

// ---- CSR build ----
__device__ __forceinline__ bool edge_valid(int e, int bank,
                                           const unsigned char* mask_ext) {
    if (bank >= 0) return g_emask[bank][e] != 0;
    if (mask_ext)  return mask_ext[e] != 0;
    return true;
}

__global__ void k_count(const int* __restrict__ dst_ext,
                        const unsigned char* __restrict__ mask_ext, int bank) {
    int e = blockIdx.x * blockDim.x + threadIdx.x;
    if (e >= ETOT) return;
    if (!edge_valid(e, bank, mask_ext)) return;
    const int* dst = (bank < 0) ? dst_ext : g_edst[bank];
    atomicAdd(&g_deg[dst[e]], 1);
}

// per-graph exclusive scan of degrees -> head/cursor (1024 threads per graph)
__global__ void k_scan(int n_per) {
    __shared__ int s[1024];
    int g = blockIdx.x, t = threadIdx.x;
    int v = (t < n_per) ? g_deg[g * n_per + t] : 0;
    s[t] = v;
    __syncthreads();
    for (int off = 1; off < 1024; off <<= 1) {
        int u = (t >= off) ? s[t - off] : 0;
        __syncthreads();
        s[t] += u;
        __syncthreads();
    }
    if (t < n_per) {
        int h = g * EPG + (s[t] - v);   // exclusive prefix
        g_headp[g * n_per + t] = h;
        g_cur[g * n_per + t]   = h;
    }
}

__global__ void k_fill(const int* __restrict__ src_ext,
                       const int* __restrict__ dst_ext,
                       const unsigned char* __restrict__ mask_ext,
                       int bank, int n_per) {
    int e = blockIdx.x * blockDim.x + threadIdx.x;
    if (e >= ETOT) return;
    if (!edge_valid(e, bank, mask_ext)) return;
    const int* src = (bank < 0) ? src_ext : g_esrc[bank];
    const int* dst = (bank < 0) ? dst_ext : g_edst[bank];
    int s = src[e], d = dst[e];
    int gbase = (s / n_per) * n_per;
    int pos = atomicAdd(&g_cur[d], 1);
    g_csr[pos] = s - gbase;             // local src index
}

// gather-max aggregation: one warp per dst node, self-loop init.
__global__ void k_aggr(int n, int n_per) {
    int w = (blockIdx.x * blockDim.x + threadIdx.x) >> 5;
    int lane = threadIdx.x & 31;
    if (w >= n) return;
    int d = w;
    int gbase = (d / n_per) * n_per;
    const float* mrow = g_msg + (size_t)d * DD;
    float m0 = mrow[lane];
    float m1 = mrow[lane + 32];
    int e   = g_headp[d];
    int end = g_cur[d];
    const float* mg = g_msg + (size_t)gbase * DD;
    for (; e + 4 <= end; e += 4) {
        int s0 = __ldg(&g_csr[e]);
        int s1 = __ldg(&g_csr[e + 1]);
        int s2 = __ldg(&g_csr[e + 2]);
        int s3 = __ldg(&g_csr[e + 3]);
        const float* r0 = mg + (size_t)s0 * DD;
        const float* r1 = mg + (size_t)s1 * DD;
        const float* r2 = mg + (size_t)s2 * DD;
        const float* r3 = mg + (size_t)s3 * DD;
        float a0 = r0[lane], b0 = r0[lane + 32];
        float a1 = r1[lane], b1 = r1[lane + 32];
        float a2 = r2[lane], b2 = r2[lane + 32];
        float a3 = r3[lane], b3 = r3[lane + 32];
        m0 = fmaxf(fmaxf(fmaxf(m0, a0), fmaxf(a1, a2)), a3);
        m1 = fmaxf(fmaxf(fmaxf(m1, b0), fmaxf(b1, b2)), b3);
    }
    for (; e < end; e++) {
        int s0 = __ldg(&g_csr[e]);
        const float* r0 = mg + (size_t)s0 * DD;
        m0 = fmaxf(m0, r0[lane]);
        m1 = fmaxf(m1, r0[lane + 32]);
    }
    float* ar = g_aggr + (size_t)d * DD;
    ar[lane]      = m0;
    ar[lane + 32] = m1;
}

// y = relu([aggr | x] @ U^T); fused score = (y.p)/||p||
__global__ void k_gemmcat(const float* __restrict__ U,
                          const float* __restrict__ p, int n) {
    __shared__ float Ut[128][64];  // Ut[i][o] = U[o*128+i]
    __shared__ float ps[64];
    __shared__ float pinv;
    for (int t = threadIdx.x; t < 128 * 64; t += blockDim.x) {
        int o = t >> 7, i = t & 127;
        Ut[i][o] = U[t];
    }
    if (threadIdx.x < 64) ps[threadIdx.x] = p[threadIdx.x];
    __syncthreads();
    if (threadIdx.x == 0) {
        float s = 0.f;
        for (int i = 0; i < 64; i++) s += ps[i] * ps[i];
        pinv = 1.0f / sqrtf(s);
    }
    __syncthreads();
    int row = blockIdx.x * blockDim.x + threadIdx.x;
    if (row >= n) return;
    const float* ar = g_aggr + (size_t)row * DD;
    const float* xr = g_x   + (size_t)row * DD;
    float acc[64];
#pragma unroll
    for (int o = 0; o < 64; o++) acc[o] = 0.f;
#pragma unroll 4
    for (int i = 0; i < 64; i++) {
        float av = ar[i];
#pragma unroll
        for (int o = 0; o < 64; o++) acc[o] = fmaf(av, Ut[i][o], acc[o]);
    }
#pragma unroll 4
    for (int i = 0; i < 64; i++) {
        float xv = xr[i];
#pragma unroll
        for (int o = 0; o < 64; o++) acc[o] = fmaf(xv, Ut[64 + i][o], acc[o]);
    }
    float* yr = g_y + (size_t)row * DD;
    float sc = 0.f;
#pragma unroll
    for (int o = 0; o < 64; o++) {
        float v = acc[o] > 0.f ? acc[o] : 0.f;
        yr[o] = v;
        sc = fmaf(v, ps[o], sc);
    }
    g_score[row] = sc * pinv;
}

// per-graph exact top-k via bitonic sort of 1024 (score, idx) pairs
__global__ void k_topk(int n_per, int k) {
    __shared__ float sc[1024];
    __shared__ int   si[1024];
    int b = blockIdx.x;
    int t = threadIdx.x;
    if (t < n_per) g_inv[b * n_per + t] = -1;
    sc[t] = (t < n_per) ? g_score[b * n_per + t] : NEG_INF;
    si[t] = t;
    __syncthreads();
    for (int ksz = 2; ksz <= 1024; ksz <<= 1) {
        for (int j = ksz >> 1; j > 0; j >>= 1) {
            int l = t ^ j;
            if (l > t) {
                bool dirDesc = ((t & ksz) == 0);
                float a = sc[t], c = sc[l];
                int ia = si[t], ic = si[l];
                bool aFirst = (a > c) || (a == c && ia < ic);
                if (aFirst != dirDesc) {
                    sc[t] = c; sc[l] = a;
                    si[t] = ic; si[l] = ia;
                }
            }
            __syncthreads();
        }
    }
    if (t < k) {
        int old = b * n_per + si[t];
        int nw  = b * k + t;
        g_selold[nw]   = old;
        g_selscale[nw] = tanhf(sc[t]);
        g_inv[old]     = nw;
    }
}

// x_new[j] = y[sel[j]] * scale[j]
__global__ void k_gather(int nk) {
    int idx = blockIdx.x * blockDim.x + threadIdx.x;
    if (idx >= nk * DD) return;
    int j = idx >> 6, d = idx & 63;
    g_x[idx] = g_y[(size_t)g_selold[j] * DD + d] * g_selscale[j];
}

__global__ void k_remap(const int* __restrict__ src_ext,
                        const int* __restrict__ dst_ext,
                        const unsigned char* __restrict__ mask_ext,
                        int in_bank, int out_bank) {
    int e = blockIdx.x * blockDim.x + threadIdx.x;
    if (e >= ETOT) return;
    const int* src = (in_bank < 0) ? src_ext : g_esrc[in_bank];
    const int* dst = (in_bank < 0) ? dst_ext : g_edst[in_bank];
    bool m;
    if (in_bank >= 0) m = g_emask[in_bank][e] != 0;
    else              m = mask_ext ? (mask_ext[e] != 0) : true;
    int ns = 0, nd = 0; bool nm = false;
    if (m) {
        ns = g_inv[src[e]];
        nd = g_inv[dst[e]];
        nm = (ns >= 0) && (nd >= 0);
    }
    g_esrc[out_bank][e]  = nm ? ns : 0;
    g_edst[out_bank][e]  = nm ? nd : 0;
    g_emask[out_bank][e] = nm ? 1 : 0;
}

// h[b] += [ max_j x , mean_j x ]   (256 threads: 64 dims x 4 row-slices)
__global__ void k_readout(int k) {
    __shared__ float smx[4][64], ssm[4][64];
    int b = blockIdx.x;
    int d = threadIdx.x & 63;
    int r = threadIdx.x >> 6;   // 0..3
    int per = (k + 3) / 4;
    int j0 = r * per;
    int j1 = min(k, j0 + per);
    float mx = NEG_INF, sm = 0.f;
    const float* base = g_x + (size_t)b * k * DD + d;
    for (int j = j0; j < j1; j++) {
        float v = base[(size_t)j * DD];
        mx = fmaxf(mx, v);
        sm += v;
    }
    smx[r][d] = mx; ssm[r][d] = sm;
    __syncthreads();
    if (r == 0) {
#pragma unroll
        for (int i = 1; i < 4; i++) {
            mx = fmaxf(mx, smx[i][d]);
            sm += ssm[i][d];
        }
        g_h[b * 128 + d]      += mx;
        g_h[b * 128 + 64 + d] += sm / (float)k;
    }
}

__global__ void k_mlp(const float* __restrict__ l1W, const float* __restrict__ l1b,
                      const float* __restrict__ l2W, const float* __restrict__ l2b,
                      const float* __restrict__ l3W, const float* __restrict__ l3b,
                      float* __restrict__ out) {
    int b = blockIdx.x;
    int o = threadIdx.x;  // 64
    __shared__ float h[128], s1[64], s2[64];
    h[o]      = g_h[b * 128 + o];
    h[o + 64] = g_h[b * 128 + 64 + o];
    __syncthreads();
    float a = l1b[o];
#pragma unroll 8
    for (int i = 0; i < 128; i++) a = fmaf(h[i], l1W[o * 128 + i], a);
    s1[o] = fmaxf(a, 0.f);
    __syncthreads();
    a = l2b[o];
#pragma unroll 8
    for (int i = 0; i < 64; i++) a = fmaf(s1[i], l2W[o * 64 + i], a);
    s2[o] = fmaxf(a, 0.f);
    __syncthreads();
    a = l3b[o];
#pragma unroll 8
    for (int i = 0; i < 64; i++) a = fmaf(s2[i], l3W[o * 64 + i], a);
    out[b * 64 + o] = 1.f / (1.f + expf(-a));
}

__global__ void k_batch(float* __restrict__ out, int out_size) {
    int i = blockIdx.x * blockDim.x + threadIdx.x;
    if (i >= BGR * K3) return;
    int pos = 8192 + i;
    if (pos < out_size) out[pos] = (float)(i / K3);
}

// ---------------- host orchestration ---------------------------------------

static void run_layer(int n, int n_per, int k,
                      const float* W, const float* b, const float* U, const float* p,
                      const int* src_ext, const int* dst_ext,
                      const unsigned char* mask_ext,
                      int in_bank, int out_bank, bool do_remap) {
    int gb = (n + 127) / 128;
    int eb = (ETOT + 255) / 256;
    k_gemm64<<<gb, 128>>>(W, b, n);
    // CSR build
    k_zero_deg<<<(n + 255) / 256, 256>>>(n);
    k_count<<<eb, 256>>>(dst_ext, mask_ext, in_bank);
    k_scan<<<BGR, 1024>>>(n_per);
    k_fill<<<eb, 256>>>(src_ext, dst_ext, mask_ext, in_bank, n_per);
    // gather-max aggregation: one warp per dst node
    k_aggr<<<(n * 32 + 255) / 256, 256>>>(n, n_per);
    k_gemmcat<<<gb, 128>>>(U, p, n);
    k_topk<<<BGR, 1024>>>(n_per, k);
    int nk = BGR * k;
    k_gather<<<(nk * DD + 255) / 256, 256>>>(nk);
    if (do_remap)
        k_remap<<<eb, 256>>>(src_ext, dst_ext, mask_ext, in_bank, out_bank);
    k_readout<<<BGR, 256>>>(k);
}

extern "C" void kernel_launch(void* const* d_in, const int* in_sizes, int n_in,
                              void* d_out, int out_size) {
    const int*   x_ids = (const int*)d_in[0];
    const int*   eidx  = (const int*)d_in[1];   // [2, E]
    const float* emb   = (const float*)d_in[2];
    const float* W1 = (const float*)d_in[3];
    const float* b1 = (const float*)d_in[4];
    const float* U1 = (const float*)d_in[5];
    const float* p1 = (const float*)d_in[6];
    const float* W2 = (const float*)d_in[7];
    const float* b2 = (const float*)d_in[8];
    const float* U2 = (const float*)d_in[9];
    const float* p2 = (const float*)d_in[10];
    const float* W3 = (const float*)d_in[11];
    const float* b3 = (const float*)d_in[12];
    const float* U3 = (const float*)d_in[13];
    const float* p3 = (const float*)d_in[14];
    const float* l1W = (const float*)d_in[15];
    const float* l1b = (const float*)d_in[16];
    const float* l2W = (const float*)d_in[17];
    const float* l2b = (const float*)d_in[18];
    const float* l3W = (const float*)d_in[19];
    const float* l3b = (const float*)d_in[20];
    float* out = (float*)d_out;

    k_embed<<<(NTOT * DD + 255) / 256, 256>>>(x_ids, emb);
    k_zero_h<<<(BGR * 2 * DD + 255) / 256, 256>>>();

    // layer 1: n = 131072, edges from input, write bank 0
    run_layer(NTOT, N0, K1, W1, b1, U1, p1,
              eidx, eidx + ETOT, nullptr, -1, 0, true);
    // layer 2: n = B*K1, edges bank0 -> bank1
    run_layer(BGR * K1, K1, K2, W2, b2, U2, p2,
              nullptr, nullptr, nullptr, 0, 1, true);
    // layer 3: n = B*K2, edges bank1, no remap needed after
    run_layer(BGR * K2, K2, K3, W3, b3, U3, p3,
              nullptr, nullptr, nullptr, 1, 0, false);

    k_mlp<<<BGR, 64>>>(l1W, l1b, l2W, l2b, l3W, l3b, out);
    k_batch<<<(BGR * K3 + 255) / 256, 256>>>(out, out_size);
}

// round 4
// speedup vs baseline: 2.8571x; 1.8339x over previous
#include <cuda_runtime.h>
#include <math.h>

// Problem constants
#define BGR   128
#define N0    1024
#define NTOT  131072
#define ETOT  2097152
#define EPG   16384
#define DD    64
#define K1    820
#define K2    656
#define K3    525

#define NEG_INF __int_as_float(0xff800000)

// ---------------- scratch ---------------------------------------------------
__device__ float g_x[NTOT * DD];
__device__ float g_y[NTOT * DD];
__device__ float g_msg[NTOT * DD];
__device__ float g_aggr[NTOT * DD];
__device__ float g_score[NTOT];
__device__ int   g_selold[NTOT];
__device__ float g_selscale[NTOT];
__device__ int   g_inv[NTOT];
__device__ int   g_esrc[2][ETOT];
__device__ int   g_edst[2][ETOT];
__device__ unsigned char g_emask[2][ETOT];
__device__ float g_h[BGR * 2 * DD];
// CSR scratch (layer 3)
__device__ int   g_deg[NTOT];
__device__ int   g_headp[NTOT];
__device__ int   g_cur[NTOT];
__device__ int   g_csr[ETOT];
// combo / LUT scratch (layers 1-2)
__device__ int   g_mask1[NTOT];
__device__ int   g_combo1[NTOT];
__device__ int   g_combo2[NTOT];
__device__ unsigned long long g_pres2[NTOT];
__device__ float g_sc1lut[64];
__device__ float g_x2lut[64 * 64];
__device__ float g_msg2lut[64 * 64];
__device__ float g_x2part[64 * 64];

// ---------------- generic small kernels -------------------------------------

__global__ void k_zero_init() {
    int i = blockIdx.x * blockDim.x + threadIdx.x;
    if (i < NTOT) g_mask1[i] = 0;
    if (i < BGR * 2 * DD) g_h[i] = 0.f;
}

__global__ void k_zero_deg(int n) {
    int i = blockIdx.x * blockDim.x + threadIdx.x;
    if (i < n) g_deg[i] = 0;
}

// ---------------- layer-1/2 combo machinery ---------------------------------

// presence of source ids per dst (layer 1, all edges valid)
__global__ void k_mask1(const int* __restrict__ src,
                        const int* __restrict__ dst,
                        const int* __restrict__ x_ids) {
    int e = blockIdx.x * blockDim.x + threadIdx.x;
    if (e >= ETOT) return;
    atomicOr(&g_mask1[dst[e]], 1 << x_ids[src[e]]);
}

// Build all LUTs in one 256-thread block (bounded regs).
__global__ void __launch_bounds__(256)
k_lut1(const float* __restrict__ emb,
       const float* __restrict__ W1, const float* __restrict__ b1,
       const float* __restrict__ U1, const float* __restrict__ p1,
       const float* __restrict__ W2, const float* __restrict__ b2,
       const float* __restrict__ U2) {
    __shared__ float s_emb[4][64], s_m1[4][64], s_amax[16][64];
    __shared__ float s_y1[64][64], s_x2[64][64];
    __shared__ float s_scale[64];
    __shared__ float s_pinv;
    int t = threadIdx.x;    // 256 threads
    s_emb[t >> 6][t & 63] = emb[t];
    if (t == 0) {
        float s = 0.f;
        for (int i = 0; i < 64; i++) s += p1[i] * p1[i];
        s_pinv = 1.0f / sqrtf(s);
    }
    __syncthreads();
    // msg1 rows (4 x 64)
    {
        int id = t >> 6, o = t & 63;
        float a = b1[o];
        for (int i = 0; i < 64; i++) a = fmaf(s_emb[id][i], W1[o * 64 + i], a);
        s_m1[id][o] = a > 0.f ? a : 0.f;
    }
    __syncthreads();
    // amax over presence masks (16 x 64)
    for (int u = t; u < 16 * 64; u += 256) {
        int mask = u >> 6, o = u & 63;
        float v = NEG_INF;
        for (int id = 0; id < 4; id++)
            if ((mask >> id) & 1) v = fmaxf(v, s_m1[id][o]);
        if (mask == 0) v = 0.f;
        s_amax[mask][o] = v;
    }
    __syncthreads();
    // y1 per combo c = id*16 + mask  (64 x 64)
    for (int u = t; u < 64 * 64; u += 256) {
        int c = u >> 6, o = u & 63;
        int id = c >> 4, mask = c & 15;
        float a = 0.f;
        for (int i = 0; i < 64; i++) a = fmaf(s_amax[mask][i], U1[o * 128 + i], a);
        for (int i = 0; i < 64; i++) a = fmaf(s_emb[id][i], U1[o * 128 + 64 + i], a);
        s_y1[c][o] = a > 0.f ? a : 0.f;
    }
    __syncthreads();
    // scores + scales
    if (t < 64) {
        float s = 0.f;
        for (int i = 0; i < 64; i++) s = fmaf(s_y1[t][i], p1[i], s);
        s *= s_pinv;
        g_sc1lut[t] = s;
        s_scale[t]  = tanhf(s);
    }
    __syncthreads();
    // x2 rows
    for (int u = t; u < 64 * 64; u += 256) {
        int c = u >> 6, d = u & 63;
        float v = s_y1[c][d] * s_scale[c];
        s_x2[c][d] = v;
        g_x2lut[u] = v;
    }
    __syncthreads();
    // msg2 rows and x-part of layer-2 concat GEMM
    for (int u = t; u < 64 * 64; u += 256) {
        int c = u >> 6, o = u & 63;
        float a = b2[o];
        for (int i = 0; i < 64; i++) a = fmaf(s_x2[c][i], W2[o * 64 + i], a);
        g_msg2lut[u] = a > 0.f ? a : 0.f;
        float x = 0.f;
        for (int i = 0; i < 64; i++) x = fmaf(s_x2[c][i], U2[o * 128 + 64 + i], x);
        g_x2part[u] = x;
    }
}

__global__ void k_combo1(const int* __restrict__ x_ids) {
    int i = blockIdx.x * blockDim.x + threadIdx.x;
    if (i >= NTOT) return;
    int id = x_ids[i];
    int c = id * 16 + (g_mask1[i] | (1 << id));
    g_combo1[i] = c;
    g_score[i]  = g_sc1lut[c];
}

// x2[j] = x2lut[combo]; also init layer-2 presence with self bit
__global__ void k_gather2(int nk) {
    int idx = blockIdx.x * blockDim.x + threadIdx.x;
    if (idx >= nk * DD) return;
    int j = idx >> 6, d = idx & 63;
    int c = g_combo1[g_selold[j]];
    g_x[idx] = g_x2lut[c * 64 + d];
    if (d == 0) {
        g_combo2[j] = c;
        g_pres2[j]  = 1ull << c;
    }
}

__global__ void k_mask2() {
    int e = blockIdx.x * blockDim.x + threadIdx.x;
    if (e >= ETOT) return;
    if (!g_emask[0][e]) return;
    int s = g_esrc[0][e], d = g_edst[0][e];
    atomicOr(&g_pres2[d], 1ull << g_combo2[s]);
}

// layer-2 aggregation: warp per node, max over present msg2 LUT rows (L1-hot)
__global__ void k_aggr2(int n) {
    int w = (blockIdx.x * blockDim.x + threadIdx.x) >> 5;
    int lane = threadIdx.x & 31;
    if (w >= n) return;
    unsigned long long m = g_pres2[w];
    float m0 = NEG_INF, m1 = NEG_INF;
    while (m) {
        int b = __ffsll(m) - 1;
        m &= m - 1;
        const float* r = g_msg2lut + b * 64;
        m0 = fmaxf(m0, __ldg(r + lane));
        m1 = fmaxf(m1, __ldg(r + lane + 32));
    }
    float* ar = g_aggr + (size_t)w * DD;
    ar[lane]      = m0;
    ar[lane + 32] = m1;
}

// layer-2 concat GEMM: y = relu(aggr @ Ua^T + x2part[combo]); fused score
__global__ void __launch_bounds__(128)
k_gemmcat2(const float* __restrict__ U, const float* __restrict__ p, int n) {
    __shared__ float Ut[64][64];   // Ut[i][o] = U[o*128+i]
    __shared__ float x2p[64][65];
    __shared__ float ps[64];
    __shared__ float pinv;
    for (int t = threadIdx.x; t < 64 * 64; t += blockDim.x) {
        int o = t >> 6, i = t & 63;
        Ut[i][o]            = U[o * 128 + i];
        x2p[t >> 6][t & 63] = g_x2part[t];
    }
    if (threadIdx.x < 64) ps[threadIdx.x] = p[threadIdx.x];
    __syncthreads();
    if (threadIdx.x == 0) {
        float s = 0.f;
        for (int i = 0; i < 64; i++) s += ps[i] * ps[i];
        pinv = 1.0f / sqrtf(s);
    }
    __syncthreads();
    int row = blockIdx.x * blockDim.x + threadIdx.x;
    if (row >= n) return;
    int c = g_combo2[row];
    const float* ar = g_aggr + (size_t)row * DD;
    float acc[64];
#pragma unroll
    for (int o = 0; o < 64; o++) acc[o] = x2p[c][o];
#pragma unroll 4
    for (int i = 0; i < 64; i++) {
        float av = ar[i];
#pragma unroll
        for (int o = 0; o < 64; o++) acc[o] = fmaf(av, Ut[i][o], acc[o]);
    }
    float* yr = g_y + (size_t)row * DD;
    float sc = 0.f;
#pragma unroll
    for (int o = 0; o < 64; o++) {
        float v = acc[o] > 0.f ? acc[o] : 0.f;
        yr[o] = v;
        sc = fmaf(v, ps[o], sc);
    }
    g_score[row] = sc * pinv;
}

// ---------------- layer-3 path ----------------------------------------------

__global__ void __launch_bounds__(128)
k_gemm64(const float* __restrict__ W, const float* __restrict__ bias, int n) {
    __shared__ float Wt[64][64];
    for (int t = threadIdx.x; t < 64 * 64; t += blockDim.x) {
        int o = t >> 6, i = t & 63;
        Wt[i][o] = W[t];
    }
    __syncthreads();
    int row = blockIdx.x * blockDim.x + threadIdx.x;
    if (row >= n) return;
    const float* xr = g_x + (size_t)row * DD;
    float acc[64];
#pragma unroll
    for (int o = 0; o < 64; o++) acc[o] = bias[o];
#pragma unroll 8
    for (int i = 0; i < 64; i++) {
        float xv = xr[i];
#pragma unroll
        for (int o = 0; o < 64; o++) acc[o] = fmaf(xv, Wt[i][o], acc[o]);
    }
    float* m = g_msg + (size_t)row * DD;
#pragma unroll
    for (int o = 0; o < 64; o++) m[o] = acc[o] > 0.f ? acc[o] : 0.f;
}

__global__ void k_count(int bank) {
    int e = blockIdx.x * blockDim.x + threadIdx.x;
    if (e >= ETOT) return;
    if (!g_emask[bank][e]) return;
    atomicAdd(&g_deg[g_edst[bank][e]], 1);
}

__global__ void __launch_bounds__(1024)
k_scan(int n_per) {
    __shared__ int s[1024];
    int g = blockIdx.x, t = threadIdx.x;
    int v = (t < n_per) ? g_deg[g * n_per + t] : 0;
    s[t] = v;
    __syncthreads();
    for (int off = 1; off < 1024; off <<= 1) {
        int u = (t >= off) ? s[t - off] : 0;
        __syncthreads();
        s[t] += u;
        __syncthreads();
    }
    if (t < n_per) {
        int h = g * EPG + (s[t] - v);
        g_headp[g * n_per + t] = h;
        g_cur[g * n_per + t]   = h;
    }
}

__global__ void k_fill(int bank, int n_per) {
    int e = blockIdx.x * blockDim.x + threadIdx.x;
    if (e >= ETOT) return;
    if (!g_emask[bank][e]) return;
    int s = g_esrc[bank][e], d = g_edst[bank][e];
    int gbase = (s / n_per) * n_per;
    int pos = atomicAdd(&g_cur[d], 1);
    g_csr[pos] = s - gbase;
}

__global__ void k_aggr(int n, int n_per) {
    int w = (blockIdx.x * blockDim.x + threadIdx.x) >> 5;
    int lane = threadIdx.x & 31;
    if (w >= n) return;
    int gbase = (w / n_per) * n_per;
    const float* mrow = g_msg + (size_t)w * DD;
    float m0 = mrow[lane];
    float m1 = mrow[lane + 32];
    int e   = g_headp[w];
    int end = g_cur[w];
    const float* mg = g_msg + (size_t)gbase * DD;
    for (; e + 4 <= end; e += 4) {
        int s0 = __ldg(&g_csr[e]);
        int s1 = __ldg(&g_csr[e + 1]);
        int s2 = __ldg(&g_csr[e + 2]);
        int s3 = __ldg(&g_csr[e + 3]);
        const float* r0 = mg + (size_t)s0 * DD;
        const float* r1 = mg + (size_t)s1 * DD;
        const float* r2 = mg + (size_t)s2 * DD;
        const float* r3 = mg + (size_t)s3 * DD;
        float a0 = r0[lane], b0 = r0[lane + 32];
        float a1 = r1[lane], b1 = r1[lane + 32];
        float a2 = r2[lane], b2 = r2[lane + 32];
        float a3 = r3[lane], b3 = r3[lane + 32];
        m0 = fmaxf(fmaxf(fmaxf(m0, a0), fmaxf(a1, a2)), a3);
        m1 = fmaxf(fmaxf(fmaxf(m1, b0), fmaxf(b1, b2)), b3);
    }
    for (; e < end; e++) {
        int s0 = __ldg(&g_csr[e]);
        const float* r0 = mg + (size_t)s0 * DD;
        m0 = fmaxf(m0, r0[lane]);
        m1 = fmaxf(m1, r0[lane + 32]);
    }
    float* ar = g_aggr + (size_t)w * DD;
    ar[lane]      = m0;
    ar[lane + 32] = m1;
}

__global__ void __launch_bounds__(128)
k_gemmcat(const float* __restrict__ U, const float* __restrict__ p, int n) {
    __shared__ float Ut[128][64];
    __shared__ float ps[64];
    __shared__ float pinv;
    for (int t = threadIdx.x; t < 128 * 64; t += blockDim.x) {
        int o = t >> 7, i = t & 127;
        Ut[i][o] = U[t];
    }
    if (threadIdx.x < 64) ps[threadIdx.x] = p[threadIdx.x];
    __syncthreads();
    if (threadIdx.x == 0) {
        float s = 0.f;
        for (int i = 0; i < 64; i++) s += ps[i] * ps[i];
        pinv = 1.0f / sqrtf(s);
    }
    __syncthreads();
    int row = blockIdx.x * blockDim.x + threadIdx.x;
    if (row >= n) return;
    const float* ar = g_aggr + (size_t)row * DD;
    const float* xr = g_x   + (size_t)row * DD;
    float acc[64];
#pragma unroll
    for (int o = 0; o < 64; o++) acc[o] = 0.f;
#pragma unroll 4
    for (int i = 0; i < 64; i++) {
        float av = ar[i];
#pragma unroll
        for (int o = 0; o < 64; o++) acc[o] = fmaf(av, Ut[i][o], acc[o]);
    }
#pragma unroll 4
    for (int i = 0; i < 64; i++) {
        float xv = xr[i];
#pragma unroll
        for (int o = 0; o < 64; o++) acc[o] = fmaf(xv, Ut[64 + i][o], acc[o]);
    }
    float* yr = g_y + (size_t)row * DD;
    float sc = 0.f;
#pragma unroll
    for (int o = 0; o < 64; o++) {
        float v = acc[o] > 0.f ? acc[o] : 0.f;
        yr[o] = v;
        sc = fmaf(v, ps[o], sc);
    }
    g_score[row] = sc * pinv;
}

// ---------------- shared pipeline pieces ------------------------------------

__global__ void __launch_bounds__(1024)
k_topk(int n_per, int k) {
    __shared__ float sc[1024];
    __shared__ int   si[1024];
    int b = blockIdx.x;
    int t = threadIdx.x;
    if (t < n_per) g_inv[b * n_per + t] = -1;
    sc[t] = (t < n_per) ? g_score[b * n_per + t] : NEG_INF;
    si[t] = t;
    __syncthreads();
    for (int ksz = 2; ksz <= 1024; ksz <<= 1) {
        for (int j = ksz >> 1; j > 0; j >>= 1) {
            int l = t ^ j;
            if (l > t) {
                bool dirDesc = ((t & ksz) == 0);
                float a = sc[t], c = sc[l];
                int ia = si[t], ic = si[l];
                bool aFirst = (a > c) || (a == c && ia < ic);
                if (aFirst != dirDesc) {
                    sc[t] = c; sc[l] = a;
                    si[t] = ic; si[l] = ia;
                }
            }
            __syncthreads();
        }
    }
    if (t < k) {
        int old = b * n_per + si[t];
        int nw  = b * k + t;
        g_selold[nw]   = old;
        g_selscale[nw] = tanhf(sc[t]);
        g_inv[old]     = nw;
    }
}

__global__ void k_gather(int nk) {
    int idx = blockIdx.x * blockDim.x + threadIdx.x;
    if (idx >= nk * DD) return;
    int j = idx >> 6, d = idx & 63;
    g_x[idx] = g_y[(size_t)g_selold[j] * DD + d] * g_selscale[j];
}

__global__ void k_remap(const int* __restrict__ src_ext,
                        const int* __restrict__ dst_ext,
                        int in_bank, int out_bank) {
    int e = blockIdx.x * blockDim.x + threadIdx.x;
    if (e >= ETOT) return;
    const int* src = (in_bank < 0) ? src_ext : g_esrc[in_bank];
    const int* dst = (in_bank < 0) ? dst_ext : g_edst[in_bank];
    bool m = (in_bank < 0) ? true : (g_emask[in_bank][e] != 0);
    int ns = 0, nd = 0; bool nm = false;
    if (m) {
        ns = g_inv[src[e]];
        nd = g_inv[dst[e]];
        nm = (ns >= 0) && (nd >= 0);
    }
    g_esrc[out_bank][e]  = nm ? ns : 0;
    g_edst[out_bank][e]  = nm ? nd : 0;
    g_emask[out_bank][e] = nm ? 1 : 0;
}

__global__ void k_readout(int k) {
    __shared__ float smx[4][64], ssm[4][64];
    int b = blockIdx.x;
    int d = threadIdx.x & 63;
    int r = threadIdx.x >> 6;
    int per = (k + 3) / 4;
    int j0 = r * per;
    int j1 = min(k, j0 + per);
    float mx = NEG_INF, sm = 0.f;
    const float* base = g_x + (size_t)b * k * DD + d;
    for (int j = j0; j < j1; j++) {
        float v = base[(size_t)j * DD];
        mx = fmaxf(mx, v);
        sm += v;
    }
    smx[r][d] = mx; ssm[r][d] = sm;
    __syncthreads();
    if (r == 0) {
#pragma unroll
        for (int i = 1; i < 4; i++) {
            mx = fmaxf(mx, smx[i][d]);
            sm += ssm[i][d];
        }
        g_h[b * 128 + d]      += mx;
        g_h[b * 128 + 64 + d] += sm / (float)k;
    }
}

__global__ void k_mlp(const float* __restrict__ l1W, const float* __restrict__ l1b,
                      const float* __restrict__ l2W, const float* __restrict__ l2b,
                      const float* __restrict__ l3W, const float* __restrict__ l3b,
                      float* __restrict__ out) {
    int b = blockIdx.x;
    int o = threadIdx.x;
    __shared__ float h[128], s1[64], s2[64];
    h[o]      = g_h[b * 128 + o];
    h[o + 64] = g_h[b * 128 + 64 + o];
    __syncthreads();
    float a = l1b[o];
#pragma unroll 8
    for (int i = 0; i < 128; i++) a = fmaf(h[i], l1W[o * 128 + i], a);
    s1[o] = fmaxf(a, 0.f);
    __syncthreads();
    a = l2b[o];
#pragma unroll 8
    for (int i = 0; i < 64; i++) a = fmaf(s1[i], l2W[o * 64 + i], a);
    s2[o] = fmaxf(a, 0.f);
    __syncthreads();
    a = l3b[o];
#pragma unroll 8
    for (int i = 0; i < 64; i++) a = fmaf(s2[i], l3W[o * 64 + i], a);
    out[b * 64 + o] = 1.f / (1.f + expf(-a));
}

__global__ void k_batch(float* __restrict__ out, int out_size) {
    int i = blockIdx.x * blockDim.x + threadIdx.x;
    if (i >= BGR * K3) return;
    int pos = 8192 + i;
    if (pos < out_size) out[pos] = (float)(i / K3);
}

// ---------------- host orchestration ---------------------------------------

extern "C" void kernel_launch(void* const* d_in, const int* in_sizes, int n_in,
                              void* d_out, int out_size) {
    const int*   x_ids = (const int*)d_in[0];
    const int*   eidx  = (const int*)d_in[1];
    const float* emb   = (const float*)d_in[2];
    const float* W1 = (const float*)d_in[3];
    const float* b1 = (const float*)d_in[4];
    const float* U1 = (const float*)d_in[5];
    const float* p1 = (const float*)d_in[6];
    const float* W2 = (const float*)d_in[7];
    const float* b2 = (const float*)d_in[8];
    const float* U2 = (const float*)d_in[9];
    const float* p2 = (const float*)d_in[10];
    const float* W3 = (const float*)d_in[11];
    const float* b3 = (const float*)d_in[12];
    const float* U3 = (const float*)d_in[13];
    const float* p3 = (const float*)d_in[14];
    const float* l1W = (const float*)d_in[15];
    const float* l1b = (const float*)d_in[16];
    const float* l2W = (const float*)d_in[17];
    const float* l2b = (const float*)d_in[18];
    const float* l3W = (const float*)d_in[19];
    const float* l3b = (const float*)d_in[20];
    float* out = (float*)d_out;

    const int eb = (ETOT + 255) / 256;

    // ---- layer 1 (combo LUT path) ----
    k_zero_init<<<(NTOT + 255) / 256, 256>>>();
    k_mask1<<<eb, 256>>>(eidx, eidx + ETOT, x_ids);
    k_lut1<<<1, 256>>>(emb, W1, b1, U1, p1, W2, b2, U2);
    k_combo1<<<(NTOT + 255) / 256, 256>>>(x_ids);
    k_topk<<<BGR, 1024>>>(N0, K1);
    int n2 = BGR * K1;
    k_gather2<<<(n2 * DD + 255) / 256, 256>>>(n2);
    k_remap<<<eb, 256>>>(eidx, eidx + ETOT, -1, 0);
    k_readout<<<BGR, 256>>>(K1);

    // ---- layer 2 (presence-mask LUT path) ----
    k_mask2<<<eb, 256>>>();
    k_aggr2<<<(n2 * 32 + 255) / 256, 256>>>(n2);
    k_gemmcat2<<<(n2 + 127) / 128, 128>>>(U2, p2, n2);
    k_topk<<<BGR, 1024>>>(K1, K2);
    int n3 = BGR * K2;
    k_gather<<<(n3 * DD + 255) / 256, 256>>>(n3);
    k_remap<<<eb, 256>>>(nullptr, nullptr, 0, 1);
    k_readout<<<BGR, 256>>>(K2);

    // ---- layer 3 (full path) ----
    k_gemm64<<<(n3 + 127) / 128, 128>>>(W3, b3, n3);
    k_zero_deg<<<(n3 + 255) / 256, 256>>>(n3);
    k_count<<<eb, 256>>>(1);
    k_scan<<<BGR, 1024>>>(K2);
    k_fill<<<eb, 256>>>(1, K2);
    k_aggr<<<(n3 * 32 + 255) / 256, 256>>>(n3, K2);
    k_gemmcat<<<(n3 + 127) / 128, 128>>>(U3, p3, n3);
    k_topk<<<BGR, 1024>>>(K2, K3);
    int nk3 = BGR * K3;
    k_gather<<<(nk3 * DD + 255) / 256, 256>>>(nk3);
    k_readout<<<BGR, 256>>>(K3);

    // ---- head ----
    k_mlp<<<BGR, 64>>>(l1W, l1b, l2W, l2b, l3W, l3b, out);
    k_batch<<<(BGR * K3 + 255) / 256, 256>>>(out, out_size);
}